// round 6
// baseline (speedup 1.0000x reference)
#include <cuda_runtime.h>

// ---------------------------------------------------------------------------
// CompositionalLoss: sum over 210 joint pairs of L1(path-sum(bones) - gt diff),
// mean over batch. Collapsed via tree prefix sums:
//   a[j] = a[par(j)] + b[j]   (a[root]=0)
//   e[j] = a[j] - t[j],  f[j] = e[j] - b[j]
//   delta(u,v) = e[u] - f[v] - b[lca]   (== e[u]-e[v] if lca==v, f[u]-f[v] if lca==u)
// ---------------------------------------------------------------------------

#define NJ 21
#define NPAIRS 210
#define SPB 64               // samples per block
#define THREADS (SPB * 3)    // 192: warp-uniform channel, lane-linear sample

// Kinematic tree (JOINTS alphabetical order): parent index per joint.
__host__ __device__ constexpr int par(int j) {
    switch (j) {
        case 0:  return 3;   // Ab        -> Hip
        case 1:  return 0;   // Chest     -> Ab
        case 2:  return 12;  // Head      -> Neck
        case 3:  return 3;   // Hip       -> Hip (root)
        case 4:  return 11;  // LFArm     -> LUArm
        case 5:  return 7;   // LFoot     -> LShin
        case 6:  return 4;   // LHand     -> LFArm
        case 7:  return 9;   // LShin     -> LThigh
        case 8:  return 1;   // LShoulder -> Chest
        case 9:  return 3;   // LThigh    -> Hip
        case 10: return 5;   // LToe      -> LFoot
        case 11: return 8;   // LUArm     -> LShoulder
        case 12: return 1;   // Neck      -> Chest
        case 13: return 20;  // RFArm     -> RUArm
        case 14: return 16;  // RFoot     -> RShin
        case 15: return 13;  // RHand     -> RFArm
        case 16: return 18;  // RShin     -> RThigh
        case 17: return 1;   // RShoulder -> Chest
        case 18: return 3;   // RThigh    -> Hip
        case 19: return 14;  // RToe      -> RFoot
        default: return 17;  // RUArm     -> RShoulder
    }
}

__host__ __device__ constexpr int depthf(int j) {
    int d = 0;
    while (par(j) != j) { j = par(j); ++d; }
    return d;
}

__host__ __device__ constexpr int lcaf(int u, int v) {
    int du = depthf(u), dv = depthf(v);
    while (du > dv) { u = par(u); --du; }
    while (dv > du) { v = par(v); --dv; }
    while (u != v) { u = par(u); v = par(v); }
    return u;
}

// p-th entry of combinations(range(21), 2)
__host__ __device__ constexpr int pair_u(int p) {
    int u = 0, c = NJ - 1;
    while (p >= c) { p -= c; ++u; --c; }
    return u;
}
__host__ __device__ constexpr int pair_v(int p) {
    int u = 0, c = NJ - 1;
    while (p >= c) { p -= c; ++u; --c; }
    return u + 1 + p;
}

// Fully-unrolled pair accumulation: all indices are template/constexpr so
// e/f/b stay register arrays (no dynamic indexing, no local memory).
template <int P, int N>
struct PairRun {
    static __device__ __forceinline__ void run(const float (&e)[NJ], const float (&f)[NJ],
                                               const float (&b)[NJ], float (&acc)[4]) {
        PairRun<P, N / 2>::run(e, f, b, acc);
        PairRun<P + N / 2, N - N / 2>::run(e, f, b, acc);
    }
};
template <int P>
struct PairRun<P, 1> {
    static __device__ __forceinline__ void run(const float (&e)[NJ], const float (&f)[NJ],
                                               const float (&b)[NJ], float (&acc)[4]) {
        constexpr int u = pair_u(P);
        constexpr int v = pair_v(P);
        constexpr int w = lcaf(u, v);
        float d;
        if constexpr (w == v)       d = e[u] - e[v];            // v is ancestor of u
        else if constexpr (w == u)  d = f[u] - f[v];            // u is ancestor of v
        else                        d = (e[u] - f[v]) - b[w];   // general
        acc[P & 3] += fabsf(d);     // FADD with |src| modifier
    }
};

__global__ __launch_bounds__(THREADS, 3)
void comploss_kernel(const float* __restrict__ gin, const float* __restrict__ gtg,
                     float* __restrict__ out, int B, float invB) {
    __shared__ __align__(16) float sIn[SPB * 63];
    __shared__ __align__(16) float sTg[SPB * 63];
    __shared__ float sRed[THREADS / 32];

    const int tid = threadIdx.x;
    const long long s0 = (long long)blockIdx.x * SPB;
    int nsamp = B - (int)s0;
    if (nsamp > SPB) nsamp = SPB;

    // ---- stage gmem -> smem, coalesced ----
    if (nsamp == SPB) {
        const float4* gi = reinterpret_cast<const float4*>(gin + s0 * 63);
        const float4* gt = reinterpret_cast<const float4*>(gtg + s0 * 63);
        float4* si = reinterpret_cast<float4*>(sIn);
        float4* st = reinterpret_cast<float4*>(sTg);
        for (int i = tid; i < (SPB * 63) / 4; i += THREADS) {
            si[i] = gi[i];
            st[i] = gt[i];
        }
    } else {
        for (int i = tid; i < nsamp * 63; i += THREADS) {
            sIn[i] = gin[s0 * 63 + i];
            sTg[i] = gtg[s0 * 63 + i];
        }
    }
    __syncthreads();

    // ---- per-(sample,channel) compute ----
    const int c = tid >> 6;        // 0..2, uniform within each warp
    const int s = tid & 63;        // lane-linear -> stride-63 smem reads are conflict-free
    float thread_sum = 0.0f;

    if (s < nsamp) {
        const float* bp = sIn + s * 63 + c;
        const float* tp = sTg + s * 63 + c;
        float b[NJ], t[NJ];
#pragma unroll
        for (int j = 0; j < NJ; ++j) { b[j] = bp[3 * j]; t[j] = tp[3 * j]; }

        // tree prefix sums (topological order, root Hip=3 has a=0)
        float a[NJ];
        a[3]  = 0.0f;
        a[0]  = b[0];
        a[1]  = a[0]  + b[1];
        a[8]  = a[1]  + b[8];
        a[12] = a[1]  + b[12];
        a[17] = a[1]  + b[17];
        a[2]  = a[12] + b[2];
        a[9]  = b[9];
        a[18] = b[18];
        a[11] = a[8]  + b[11];
        a[20] = a[17] + b[20];
        a[7]  = a[9]  + b[7];
        a[16] = a[18] + b[16];
        a[4]  = a[11] + b[4];
        a[13] = a[20] + b[13];
        a[5]  = a[7]  + b[5];
        a[14] = a[16] + b[14];
        a[6]  = a[4]  + b[6];
        a[15] = a[13] + b[15];
        a[10] = a[5]  + b[10];
        a[19] = a[14] + b[19];

        float e[NJ], f[NJ];
#pragma unroll
        for (int j = 0; j < NJ; ++j) {
            e[j] = a[j] - t[j];
            f[j] = e[j] - b[j];
        }

        float acc[4] = {0.0f, 0.0f, 0.0f, 0.0f};
        PairRun<0, NPAIRS>::run(e, f, b, acc);
        thread_sum = (acc[0] + acc[1]) + (acc[2] + acc[3]);
    }

    // ---- reduction: warp shuffle -> smem -> one atomic per block ----
#pragma unroll
    for (int o = 16; o > 0; o >>= 1)
        thread_sum += __shfl_down_sync(0xffffffffu, thread_sum, o);
    if ((tid & 31) == 0) sRed[tid >> 5] = thread_sum;
    __syncthreads();
    if (tid == 0) {
        float bs = 0.0f;
#pragma unroll
        for (int wI = 0; wI < THREADS / 32; ++wI) bs += sRed[wI];
        atomicAdd(out, bs * invB);
    }
}

__global__ void zero_out_kernel(float* out) { out[0] = 0.0f; }

extern "C" void kernel_launch(void* const* d_in, const int* in_sizes, int n_in,
                              void* d_out, int out_size) {
    const float* gin = (const float*)d_in[0];   // input  [B, 63]
    const float* gtg = (const float*)d_in[1];   // target [B, 63]
    float* out = (float*)d_out;                 // [1] float32

    const int B = in_sizes[0] / (NJ * 3);
    const int blocks = (B + SPB - 1) / SPB;

    zero_out_kernel<<<1, 1>>>(out);
    comploss_kernel<<<blocks, THREADS>>>(gin, gtg, out, B, 1.0f / (float)B);
}

// round 7
// speedup vs baseline: 1.1345x; 1.1345x over previous
#include <cuda_runtime.h>
#include <cstdint>

// ---------------------------------------------------------------------------
// CompositionalLoss collapsed via tree prefix sums:
//   a[j] = a[par(j)] + b[j]   (a[root]=0)
//   e[j] = a[j] - t[j],  f[j] = e[j] - b[j]
//   delta(u,v) = e[u] - f[v] - b[lca]
//     lca==v -> e[u]-e[v];  lca==u -> f[u]-f[v]
//   Tree has only two branching nodes (Hip=3, Chest=1), so every cross-pair
//   LCA is 1 or 3 -> only scalars b1, b3 needed besides e[] and f[].
// ---------------------------------------------------------------------------

#define NJ 21
#define NPAIRS 210
#define SPB 64               // samples per block
#define THREADS 192          // 3 channels x 64 samples; warp-uniform channel
#define MAXBLOCKS 4096

__device__ float g_partials[MAXBLOCKS];
__device__ unsigned int g_count = 0;   // reset by last block every launch

// Kinematic tree (JOINTS alphabetical): parent index per joint.
__host__ __device__ constexpr int par(int j) {
    switch (j) {
        case 0:  return 3;   case 1:  return 0;   case 2:  return 12;
        case 3:  return 3;   case 4:  return 11;  case 5:  return 7;
        case 6:  return 4;   case 7:  return 9;   case 8:  return 1;
        case 9:  return 3;   case 10: return 5;   case 11: return 8;
        case 12: return 1;   case 13: return 20;  case 14: return 16;
        case 15: return 13;  case 16: return 18;  case 17: return 1;
        case 18: return 3;   case 19: return 14;  default: return 17;
    }
}
__host__ __device__ constexpr int depthf(int j) {
    int d = 0;
    while (par(j) != j) { j = par(j); ++d; }
    return d;
}
__host__ __device__ constexpr int lcaf(int u, int v) {
    int du = depthf(u), dv = depthf(v);
    while (du > dv) { u = par(u); --du; }
    while (dv > du) { v = par(v); --dv; }
    while (u != v) { u = par(u); v = par(v); }
    return u;
}
__host__ __device__ constexpr int pair_u(int p) {
    int u = 0, c = NJ - 1;
    while (p >= c) { p -= c; ++u; --c; }
    return u;
}
__host__ __device__ constexpr int pair_v(int p) {
    int u = 0, c = NJ - 1;
    while (p >= c) { p -= c; ++u; --c; }
    return u + 1 + p;
}

// Fully-unrolled pair accumulation with compile-time indices.
template <int P, int N>
struct PairRun {
    static __device__ __forceinline__ void run(const float (&e)[NJ], const float (&f)[NJ],
                                               float b1, float b3, float (&acc)[4]) {
        PairRun<P, N / 2>::run(e, f, b1, b3, acc);
        PairRun<P + N / 2, N - N / 2>::run(e, f, b1, b3, acc);
    }
};
template <int P>
struct PairRun<P, 1> {
    static __device__ __forceinline__ void run(const float (&e)[NJ], const float (&f)[NJ],
                                               float b1, float b3, float (&acc)[4]) {
        constexpr int u = pair_u(P);
        constexpr int v = pair_v(P);
        constexpr int w = lcaf(u, v);
        static_assert(w == u || w == v || w == 1 || w == 3, "unexpected LCA");
        float d;
        if constexpr (w == v)       d = e[u] - e[v];
        else if constexpr (w == u)  d = f[u] - f[v];
        else if constexpr (w == 1)  d = (e[u] - f[v]) - b1;
        else                        d = (e[u] - f[v]) - b3;
        acc[P & 3] += fabsf(d);     // FADD with |src| modifier
    }
};

__device__ __forceinline__ uint32_t smem_u32(const void* p) {
    return (uint32_t)__cvta_generic_to_shared(p);
}
__device__ __forceinline__ void cp_async16(uint32_t dst, const void* src) {
    asm volatile("cp.async.cg.shared.global [%0], [%1], 16;" :: "r"(dst), "l"(src));
}

__global__ __launch_bounds__(THREADS, 5)
void comploss_kernel(const float* __restrict__ gin, const float* __restrict__ gtg,
                     float* __restrict__ out, int B, float invB, int nblocks) {
    __shared__ __align__(16) float sIn[SPB * 63];
    __shared__ __align__(16) float sTg[SPB * 63];
    __shared__ float sRed[THREADS / 32];
    __shared__ bool sLast;

    const int tid = threadIdx.x;
    const long long s0 = (long long)blockIdx.x * SPB;
    int nsamp = B - (int)s0;
    if (nsamp > SPB) nsamp = SPB;

    // ---- stage gmem -> smem via cp.async (register-free, deep MLP) ----
    if (nsamp == SPB) {
        const float4* gi = reinterpret_cast<const float4*>(gin + s0 * 63);
        const float4* gt = reinterpret_cast<const float4*>(gtg + s0 * 63);
        const uint32_t si = smem_u32(sIn);
        const uint32_t st = smem_u32(sTg);
        for (int i = tid; i < (SPB * 63) / 4; i += THREADS) {
            cp_async16(si + i * 16, gi + i);
            cp_async16(st + i * 16, gt + i);
        }
        asm volatile("cp.async.commit_group;");
        asm volatile("cp.async.wait_group 0;");
    } else {
        for (int i = tid; i < nsamp * 63; i += THREADS) {
            sIn[i] = gin[s0 * 63 + i];
            sTg[i] = gtg[s0 * 63 + i];
        }
    }
    __syncthreads();

    // ---- per-(sample,channel) compute ----
    const int c = tid >> 6;        // uniform within each warp
    const int s = tid & 63;        // stride-63 smem reads: conflict-free
    float thread_sum = 0.0f;

    if (s < nsamp) {
        const float* bp = sIn + s * 63 + c;
        const float* tp = sTg + s * 63 + c;

        float e[NJ], f[NJ], a[NJ];
        float b1, b3;
        // Per joint: load b,t from smem at use; only e/f/b1/b3 stay live.
#define LOADJ(j, apar)                                    \
        { float bb = bp[3 * (j)]; float tt = tp[3 * (j)]; \
          a[j] = (apar) + bb;                             \
          e[j] = a[j] - tt;                               \
          f[j] = e[j] - bb; }

        // root Hip=3
        { float bb = bp[9]; float tt = tp[9];
          a[3] = 0.0f; e[3] = -tt; f[3] = -tt - bb; b3 = bb; }
        LOADJ(0,  a[3]);
        { float bb = bp[3]; float tt = tp[3];            // j=1 (Chest), keep b1
          a[1] = a[0] + bb; e[1] = a[1] - tt; f[1] = e[1] - bb; b1 = bb; }
        LOADJ(8,  a[1]);
        LOADJ(12, a[1]);
        LOADJ(17, a[1]);
        LOADJ(2,  a[12]);
        LOADJ(9,  a[3]);
        LOADJ(18, a[3]);
        LOADJ(11, a[8]);
        LOADJ(20, a[17]);
        LOADJ(7,  a[9]);
        LOADJ(16, a[18]);
        LOADJ(4,  a[11]);
        LOADJ(13, a[20]);
        LOADJ(5,  a[7]);
        LOADJ(14, a[16]);
        LOADJ(6,  a[4]);
        LOADJ(15, a[13]);
        LOADJ(10, a[5]);
        LOADJ(19, a[14]);
#undef LOADJ

        float acc[4] = {0.0f, 0.0f, 0.0f, 0.0f};
        PairRun<0, NPAIRS>::run(e, f, b1, b3, acc);
        thread_sum = (acc[0] + acc[1]) + (acc[2] + acc[3]);
    }

    // ---- block reduction ----
#pragma unroll
    for (int o = 16; o > 0; o >>= 1)
        thread_sum += __shfl_down_sync(0xffffffffu, thread_sum, o);
    if ((tid & 31) == 0) sRed[tid >> 5] = thread_sum;
    __syncthreads();
    if (tid == 0) {
        float bs = 0.0f;
#pragma unroll
        for (int wI = 0; wI < THREADS / 32; ++wI) bs += sRed[wI];
        g_partials[blockIdx.x] = bs;
        __threadfence();
        unsigned int old = atomicAdd(&g_count, 1u);
        sLast = (old == (unsigned int)(nblocks - 1));
    }
    __syncthreads();

    // ---- last block finishes the global reduction ----
    if (sLast) {
        __threadfence();
        float v = 0.0f;
        for (int i = tid; i < nblocks; i += THREADS) v += g_partials[i];
#pragma unroll
        for (int o = 16; o > 0; o >>= 1)
            v += __shfl_down_sync(0xffffffffu, v, o);
        if ((tid & 31) == 0) sRed[tid >> 5] = v;
        __syncthreads();
        if (tid == 0) {
            float tot = 0.0f;
#pragma unroll
            for (int wI = 0; wI < THREADS / 32; ++wI) tot += sRed[wI];
            out[0] = tot * invB;
            g_count = 0;   // self-reset: deterministic across graph replays
        }
    }
}

extern "C" void kernel_launch(void* const* d_in, const int* in_sizes, int n_in,
                              void* d_out, int out_size) {
    const float* gin = (const float*)d_in[0];   // input  [B, 63]
    const float* gtg = (const float*)d_in[1];   // target [B, 63]
    float* out = (float*)d_out;                 // [1] float32

    const int B = in_sizes[0] / (NJ * 3);
    int nblocks = (B + SPB - 1) / SPB;
    if (nblocks > MAXBLOCKS) nblocks = MAXBLOCKS;  // B=65536 -> 1024, safe

    comploss_kernel<<<nblocks, THREADS>>>(gin, gtg, out, B, 1.0f / (float)B, nblocks);
}

// round 8
// speedup vs baseline: 1.1600x; 1.0225x over previous
#include <cuda_runtime.h>
#include <cstdint>

// ---------------------------------------------------------------------------
// CompositionalLoss collapsed via tree prefix sums:
//   a[j] = a[par(j)] + b[j]   (a[root]=0)
//   e[j] = a[j] - t[j],  f[j] = e[j] - b[j]
//   delta(u,v) = e[u] - f[v] - b[lca]
//     lca==v -> e[u]-e[v];  lca==u -> f[u]-f[v]
//   Only branching nodes are Hip(3) and Chest(1) -> cross-pair LCA is 1 or 3.
// Persistent blocks, 2-stage cp.async double buffer, one wave of 444 blocks.
// ---------------------------------------------------------------------------

#define NJ 21
#define NPAIRS 210
#define SPB 64               // samples per tile
#define THREADS 192          // 3 channels x 64 samples; warp-uniform channel
#define GRID_MAX 444         // 3 blocks/SM x 148 SMs = one full wave
#define TILE_FLOATS (SPB * 63)
#define STAGE_FLOATS (TILE_FLOATS * 2)          // In + Tg per stage
#define SMEM_BYTES (2 * STAGE_FLOATS * 4)       // 64512 B

__device__ float g_partials[GRID_MAX];
__device__ unsigned int g_count = 0;   // self-resets each launch (graph-safe)

// Kinematic tree (JOINTS alphabetical): parent index per joint.
__host__ __device__ constexpr int par(int j) {
    switch (j) {
        case 0:  return 3;   case 1:  return 0;   case 2:  return 12;
        case 3:  return 3;   case 4:  return 11;  case 5:  return 7;
        case 6:  return 4;   case 7:  return 9;   case 8:  return 1;
        case 9:  return 3;   case 10: return 5;   case 11: return 8;
        case 12: return 1;   case 13: return 20;  case 14: return 16;
        case 15: return 13;  case 16: return 18;  case 17: return 1;
        case 18: return 3;   case 19: return 14;  default: return 17;
    }
}
__host__ __device__ constexpr int depthf(int j) {
    int d = 0;
    while (par(j) != j) { j = par(j); ++d; }
    return d;
}
__host__ __device__ constexpr int lcaf(int u, int v) {
    int du = depthf(u), dv = depthf(v);
    while (du > dv) { u = par(u); --du; }
    while (dv > du) { v = par(v); --dv; }
    while (u != v) { u = par(u); v = par(v); }
    return u;
}
__host__ __device__ constexpr int pair_u(int p) {
    int u = 0, c = NJ - 1;
    while (p >= c) { p -= c; ++u; --c; }
    return u;
}
__host__ __device__ constexpr int pair_v(int p) {
    int u = 0, c = NJ - 1;
    while (p >= c) { p -= c; ++u; --c; }
    return u + 1 + p;
}

// Fully-unrolled pair accumulation with compile-time indices.
template <int P, int N>
struct PairRun {
    static __device__ __forceinline__ void run(const float (&e)[NJ], const float (&f)[NJ],
                                               float b1, float b3, float (&acc)[4]) {
        PairRun<P, N / 2>::run(e, f, b1, b3, acc);
        PairRun<P + N / 2, N - N / 2>::run(e, f, b1, b3, acc);
    }
};
template <int P>
struct PairRun<P, 1> {
    static __device__ __forceinline__ void run(const float (&e)[NJ], const float (&f)[NJ],
                                               float b1, float b3, float (&acc)[4]) {
        constexpr int u = pair_u(P);
        constexpr int v = pair_v(P);
        constexpr int w = lcaf(u, v);
        static_assert(w == u || w == v || w == 1 || w == 3, "unexpected LCA");
        float d;
        if constexpr (w == v)       d = e[u] - e[v];
        else if constexpr (w == u)  d = f[u] - f[v];
        else if constexpr (w == 1)  d = (e[u] - f[v]) - b1;
        else                        d = (e[u] - f[v]) - b3;
        acc[P & 3] += fabsf(d);     // FADD with |src| modifier
    }
};

__device__ __forceinline__ uint32_t smem_u32(const void* p) {
    return (uint32_t)__cvta_generic_to_shared(p);
}
__device__ __forceinline__ void cp_async16(uint32_t dst, const void* src) {
    asm volatile("cp.async.cg.shared.global [%0], [%1], 16;" :: "r"(dst), "l"(src));
}

__global__ __launch_bounds__(THREADS, 3)
void comploss_kernel(const float* __restrict__ gin, const float* __restrict__ gtg,
                     float* __restrict__ out, int B, float invB, int ntiles) {
    extern __shared__ __align__(16) float sm[];
    __shared__ float sRed[THREADS / 32];
    __shared__ bool sLast;

    const int tid = threadIdx.x;
    const int grid = gridDim.x;

    // ---- tile fill: gmem -> smem[stage] via cp.async ----
    auto fill = [&](int stage, int tile) {
        float* sIn = sm + stage * STAGE_FLOATS;
        float* sTg = sIn + TILE_FLOATS;
        const long long s0 = (long long)tile * SPB;
        int nsamp = B - (int)s0;
        if (nsamp >= SPB) {
            const float4* gi = reinterpret_cast<const float4*>(gin + s0 * 63);
            const float4* gt = reinterpret_cast<const float4*>(gtg + s0 * 63);
            const uint32_t si = smem_u32(sIn);
            const uint32_t st = smem_u32(sTg);
            for (int i = tid; i < TILE_FLOATS / 4; i += THREADS) {
                cp_async16(si + i * 16, gi + i);
                cp_async16(st + i * 16, gt + i);
            }
        } else {
            for (int i = tid; i < nsamp * 63; i += THREADS) {
                sIn[i] = gin[s0 * 63 + i];
                sTg[i] = gtg[s0 * 63 + i];
            }
        }
        asm volatile("cp.async.commit_group;");
    };

    const int c = tid >> 6;        // channel, uniform within each warp
    const int s = tid & 63;        // sample-in-tile; stride-63 smem: conflict-free
    float thread_total = 0.0f;

    // ---- prologue: prefetch first tile ----
    if (blockIdx.x < ntiles) fill(0, blockIdx.x);

    int stage = 0;
    for (int tile = blockIdx.x; tile < ntiles; tile += grid) {
        const int next = tile + grid;
        if (next < ntiles) {
            fill(stage ^ 1, next);
            asm volatile("cp.async.wait_group 1;" ::: "memory");
        } else {
            asm volatile("cp.async.wait_group 0;" ::: "memory");
        }
        __syncthreads();

        int nsamp = B - tile * SPB;
        if (nsamp > SPB) nsamp = SPB;

        if (s < nsamp) {
            const float* sIn = sm + stage * STAGE_FLOATS;
            const float* sTg = sIn + TILE_FLOATS;
            const float* bp = sIn + s * 63 + c;
            const float* tp = sTg + s * 63 + c;

            // Hoisted independent loads -> deep MLP (regs are free: smem-bound)
            float bb[NJ], tt[NJ];
#pragma unroll
            for (int j = 0; j < NJ; ++j) { bb[j] = bp[3 * j]; tt[j] = tp[3 * j]; }

            // tree prefix sums (topological order, root Hip=3: a=0)
            float a[NJ];
            a[3]  = 0.0f;
            a[0]  = bb[0];
            a[1]  = a[0]  + bb[1];
            a[8]  = a[1]  + bb[8];
            a[12] = a[1]  + bb[12];
            a[17] = a[1]  + bb[17];
            a[2]  = a[12] + bb[2];
            a[9]  = bb[9];
            a[18] = bb[18];
            a[11] = a[8]  + bb[11];
            a[20] = a[17] + bb[20];
            a[7]  = a[9]  + bb[7];
            a[16] = a[18] + bb[16];
            a[4]  = a[11] + bb[4];
            a[13] = a[20] + bb[13];
            a[5]  = a[7]  + bb[5];
            a[14] = a[16] + bb[14];
            a[6]  = a[4]  + bb[6];
            a[15] = a[13] + bb[15];
            a[10] = a[5]  + bb[10];
            a[19] = a[14] + bb[19];

            float e[NJ], f[NJ];
#pragma unroll
            for (int j = 0; j < NJ; ++j) {
                e[j] = a[j] - tt[j];
                f[j] = e[j] - bb[j];
            }

            float acc[4] = {0.0f, 0.0f, 0.0f, 0.0f};
            PairRun<0, NPAIRS>::run(e, f, bb[1], bb[3], acc);
            thread_total += (acc[0] + acc[1]) + (acc[2] + acc[3]);
        }

        __syncthreads();   // everyone done reading smem[stage] before refill
        stage ^= 1;
    }

    // ---- block reduction (once per block) ----
#pragma unroll
    for (int o = 16; o > 0; o >>= 1)
        thread_total += __shfl_down_sync(0xffffffffu, thread_total, o);
    if ((tid & 31) == 0) sRed[tid >> 5] = thread_total;
    __syncthreads();
    if (tid == 0) {
        float bs = 0.0f;
#pragma unroll
        for (int wI = 0; wI < THREADS / 32; ++wI) bs += sRed[wI];
        g_partials[blockIdx.x] = bs;
        __threadfence();
        unsigned int old = atomicAdd(&g_count, 1u);
        sLast = (old == (unsigned int)(gridDim.x - 1));
    }
    __syncthreads();

    // ---- last block finishes the global reduction ----
    if (sLast) {
        __threadfence();
        float v = 0.0f;
        for (int i = tid; i < gridDim.x; i += THREADS) v += g_partials[i];
#pragma unroll
        for (int o = 16; o > 0; o >>= 1)
            v += __shfl_down_sync(0xffffffffu, v, o);
        if ((tid & 31) == 0) sRed[tid >> 5] = v;
        __syncthreads();
        if (tid == 0) {
            float tot = 0.0f;
#pragma unroll
            for (int wI = 0; wI < THREADS / 32; ++wI) tot += sRed[wI];
            out[0] = tot * invB;
            g_count = 0;   // deterministic across graph replays
        }
    }
}

extern "C" void kernel_launch(void* const* d_in, const int* in_sizes, int n_in,
                              void* d_out, int out_size) {
    const float* gin = (const float*)d_in[0];   // input  [B, 63]
    const float* gtg = (const float*)d_in[1];   // target [B, 63]
    float* out = (float*)d_out;                 // [1] float32

    const int B = in_sizes[0] / (NJ * 3);
    const int ntiles = (B + SPB - 1) / SPB;
    int grid = ntiles < GRID_MAX ? ntiles : GRID_MAX;

    static bool attr_set = false;
    if (!attr_set) {
        cudaFuncSetAttribute(comploss_kernel,
                             cudaFuncAttributeMaxDynamicSharedMemorySize, SMEM_BYTES);
        attr_set = true;
    }

    comploss_kernel<<<grid, THREADS, SMEM_BYTES>>>(gin, gtg, out, B,
                                                   1.0f / (float)B, ntiles);
}